// round 1
// baseline (speedup 1.0000x reference)
#include <cuda_runtime.h>
#include <math.h>

#define BB 4
#define TT 4096
#define CC 2048
#define HH 128
#define NROW (BB * TT)          // 16384

// Scratch for Q, K, V projections: [B*T, H] each, fp32. 25 MB total.
__device__ float g_q[NROW * HH];
__device__ float g_k[NROW * HH];
__device__ float g_v[NROW * HH];

// ---------------------------------------------------------------------------
// Kernel 1: fused QKV projection.  C[row, h] = sum_k idx[row,k] * W[h,k]
// Tiles: BM=128 rows x BN=128 heads x BK=16.  256 threads, 8x8 micro-tile.
// grid = (128 row tiles, 3 weights)
// ---------------------------------------------------------------------------
#define QBK 16
#define QPAD 132   // smem row stride (floats), keeps float4 alignment

__global__ __launch_bounds__(256, 2)
void qkv_kernel(const float* __restrict__ idx,
                const float* __restrict__ Wq,
                const float* __restrict__ Wk,
                const float* __restrict__ Wv)
{
    __shared__ float As[QBK][QPAD];
    __shared__ float Bs[QBK][QPAD];

    const int rowTile = blockIdx.x;          // 0..127
    const int w = blockIdx.y;                // 0..2
    const float* __restrict__ Wp = (w == 0) ? Wq : (w == 1) ? Wk : Wv;
    float* __restrict__ Out = (w == 0) ? g_q : (w == 1) ? g_k : g_v;

    const int tid = threadIdx.x;
    const int tr = tid >> 4;                 // 0..15 -> 8 rows each
    const int tc = tid & 15;                 // 0..15 -> 8 strided cols each
    const int row0 = rowTile * 128;

    float acc[8][8];
#pragma unroll
    for (int i = 0; i < 8; i++)
#pragma unroll
        for (int j = 0; j < 8; j++) acc[i][j] = 0.f;

    for (int k0 = 0; k0 < CC; k0 += QBK) {
        // Load A (128x16) and B (128x16) tiles, transposed into [k][m] layout.
#pragma unroll
        for (int i = 0; i < 2; i++) {
            int fi = tid + i * 256;          // float4 index 0..511
            int r  = fi >> 2;                // 0..127
            int c4 = (fi & 3) * 4;           // 0,4,8,12
            float4 va = *(const float4*)(idx + (size_t)(row0 + r) * CC + k0 + c4);
            As[c4 + 0][r] = va.x; As[c4 + 1][r] = va.y;
            As[c4 + 2][r] = va.z; As[c4 + 3][r] = va.w;
            float4 vb = *(const float4*)(Wp + (size_t)r * CC + k0 + c4);
            Bs[c4 + 0][r] = vb.x; Bs[c4 + 1][r] = vb.y;
            Bs[c4 + 2][r] = vb.z; Bs[c4 + 3][r] = vb.w;
        }
        __syncthreads();

#pragma unroll
        for (int k = 0; k < QBK; k++) {
            float a[8], b[8];
            *(float4*)(a)     = *(const float4*)&As[k][tr * 8];
            *(float4*)(a + 4) = *(const float4*)&As[k][tr * 8 + 4];
#pragma unroll
            for (int j = 0; j < 8; j++) b[j] = Bs[k][tc + 16 * j];
#pragma unroll
            for (int i = 0; i < 8; i++)
#pragma unroll
                for (int j = 0; j < 8; j++)
                    acc[i][j] = fmaf(a[i], b[j], acc[i][j]);
        }
        __syncthreads();
    }

#pragma unroll
    for (int i = 0; i < 8; i++) {
        const size_t r = (size_t)(row0 + tr * 8 + i);
#pragma unroll
        for (int j = 0; j < 8; j++)
            Out[r * HH + tc + 16 * j] = acc[i][j];
    }
}

// ---------------------------------------------------------------------------
// Kernel 2: causal attention with online softmax (flash-attention style).
// NOTE the swapped roles from the reference: S[i,j] = scale * <k_i, q_j>,
// softmax over j (causal j<=i), O[i,:] = sum_j P[i,j] * v_j.
// Per CTA: one batch b, 64 rows i (K rows resident); loop over 64-wide
// j-tiles of Q and V.  256 threads.
// ---------------------------------------------------------------------------
#define AR 64
#define AC 64
#define KST 132     // smem row stride for K/Q/V tiles
#define SST 68      // smem row stride for the score tile

#define ATTN_SMEM_FLOATS (3 * AR * KST + AR * SST + 3 * AR)
#define ATTN_SMEM_BYTES  (ATTN_SMEM_FLOATS * 4)

__global__ __launch_bounds__(256, 1)
void attn_kernel(float* __restrict__ out)
{
    extern __shared__ float sm[];
    float* Ks  = sm;                         // [64][132]
    float* Qs  = Ks + AR * KST;              // [64][132]
    float* Vs  = Qs + AR * KST;              // [64][132]
    float* Ss  = Vs + AR * KST;              // [64][68]
    float* m_s = Ss + AR * SST;              // [64] running max
    float* l_s = m_s + AR;                   // [64] running sum
    float* a_s = l_s + AR;                   // [64] rescale factor

    const int b   = blockIdx.y;
    const int ib  = (int)gridDim.x - 1 - (int)blockIdx.x;  // big blocks first
    const int i0  = ib * AR;
    const int tid = threadIdx.x;
    const int tr  = tid >> 4;                // 0..15
    const int tc  = tid & 15;                // 0..15

    const float scale = rsqrtf((float)CC);

    // Load resident K rows [i0, i0+64)
    const float* kbase = g_k + ((size_t)b * TT + i0) * HH;
#pragma unroll
    for (int i = 0; i < 8; i++) {
        int fi = tid + i * 256;              // float4 id, 0..2047
        int r  = fi >> 5;                    // 0..63
        int c  = (fi & 31) * 4;              // 0..124
        *(float4*)&Ks[r * KST + c] = *(const float4*)(kbase + r * HH + c);
    }
    if (tid < AR) { m_s[tid] = -INFINITY; l_s[tid] = 0.f; }

    float o[4][8];
#pragma unroll
    for (int i = 0; i < 4; i++)
#pragma unroll
        for (int j = 0; j < 8; j++) o[i][j] = 0.f;

    __syncthreads();

    for (int jb = 0; jb <= ib; jb++) {
        const int j0 = jb * AC;
        const float* qbase = g_q + ((size_t)b * TT + j0) * HH;
        const float* vbase = g_v + ((size_t)b * TT + j0) * HH;
#pragma unroll
        for (int i = 0; i < 8; i++) {
            int fi = tid + i * 256;
            int r  = fi >> 5;
            int c  = (fi & 31) * 4;
            *(float4*)&Qs[r * KST + c] = *(const float4*)(qbase + r * HH + c);
            *(float4*)&Vs[r * KST + c] = *(const float4*)(vbase + r * HH + c);
        }
        __syncthreads();

        // ---- S = scale * Ks . Qs^T  (4x4 per thread, cols strided by 16) ----
        float s[4][4];
#pragma unroll
        for (int i = 0; i < 4; i++)
#pragma unroll
            for (int j = 0; j < 4; j++) s[i][j] = 0.f;

#pragma unroll 4
        for (int h = 0; h < HH; h += 4) {
            float4 kk[4], qq[4];
#pragma unroll
            for (int i = 0; i < 4; i++)
                kk[i] = *(const float4*)&Ks[(tr * 4 + i) * KST + h];
#pragma unroll
            for (int j = 0; j < 4; j++)
                qq[j] = *(const float4*)&Qs[(tc + 16 * j) * KST + h];
#pragma unroll
            for (int i = 0; i < 4; i++)
#pragma unroll
                for (int j = 0; j < 4; j++) {
                    s[i][j] = fmaf(kk[i].x, qq[j].x, s[i][j]);
                    s[i][j] = fmaf(kk[i].y, qq[j].y, s[i][j]);
                    s[i][j] = fmaf(kk[i].z, qq[j].z, s[i][j]);
                    s[i][j] = fmaf(kk[i].w, qq[j].w, s[i][j]);
                }
        }

#pragma unroll
        for (int i = 0; i < 4; i++) {
            const int r = tr * 4 + i;
#pragma unroll
            for (int j = 0; j < 4; j++) {
                const int c = tc + 16 * j;
                float val = s[i][j] * scale;
                if (jb == ib && c > r) val = -INFINITY;   // causal mask (diag tile)
                Ss[r * SST + c] = val;
            }
        }
        __syncthreads();

        // ---- online softmax: 4 threads per row, 16 cols each ----
        {
            const int row = tid >> 2;
            const int q4  = tid & 3;
            float* srow = Ss + row * SST + q4 * 16;
            float mx = -INFINITY;
#pragma unroll
            for (int c = 0; c < 16; c++) mx = fmaxf(mx, srow[c]);
            mx = fmaxf(mx, __shfl_xor_sync(0xffffffffu, mx, 1));
            mx = fmaxf(mx, __shfl_xor_sync(0xffffffffu, mx, 2));
            const float m_old = m_s[row];
            const float m_new = fmaxf(m_old, mx);
            float ps = 0.f;
#pragma unroll
            for (int c = 0; c < 16; c++) {
                float p = __expf(srow[c] - m_new);
                srow[c] = p;
                ps += p;
            }
            ps += __shfl_xor_sync(0xffffffffu, ps, 1);
            ps += __shfl_xor_sync(0xffffffffu, ps, 2);
            if (q4 == 0) {
                const float al = __expf(m_old - m_new);  // 0 on first block
                a_s[row] = al;
                l_s[row] = l_s[row] * al + ps;
                m_s[row] = m_new;
            }
        }
        __syncthreads();

        // ---- O = O * alpha + P @ V  (4 rows x 8 strided cols per thread) ----
        {
            float al[4];
#pragma unroll
            for (int i = 0; i < 4; i++) al[i] = a_s[tr * 4 + i];
#pragma unroll
            for (int i = 0; i < 4; i++)
#pragma unroll
                for (int j = 0; j < 8; j++) o[i][j] *= al[i];

#pragma unroll 4
            for (int jj = 0; jj < AC; jj++) {
                float p[4];
#pragma unroll
                for (int i = 0; i < 4; i++) p[i] = Ss[(tr * 4 + i) * SST + jj];
                float vv[8];
#pragma unroll
                for (int j = 0; j < 8; j++) vv[j] = Vs[jj * KST + tc + 16 * j];
#pragma unroll
                for (int i = 0; i < 4; i++)
#pragma unroll
                    for (int j = 0; j < 8; j++)
                        o[i][j] = fmaf(p[i], vv[j], o[i][j]);
            }
        }
        __syncthreads();   // protect Qs/Vs/Ss before next tile load
    }

    // ---- epilogue: divide by l, write out ----
    float inv_l[4];
#pragma unroll
    for (int i = 0; i < 4; i++) inv_l[i] = 1.f / l_s[tr * 4 + i];

    float* obase = out + ((size_t)b * TT + i0) * HH;
#pragma unroll
    for (int i = 0; i < 4; i++)
#pragma unroll
        for (int j = 0; j < 8; j++)
            obase[(size_t)(tr * 4 + i) * HH + tc + 16 * j] = o[i][j] * inv_l[i];
}

// ---------------------------------------------------------------------------
extern "C" void kernel_launch(void* const* d_in, const int* in_sizes, int n_in,
                              void* d_out, int out_size)
{
    const float* idx = (const float*)d_in[0];
    const float* Wq  = (const float*)d_in[1];
    const float* Wk  = (const float*)d_in[2];
    const float* Wv  = (const float*)d_in[3];
    float* out = (float*)d_out;

    // Idempotent, capture-safe (not a stream op, no allocation).
    cudaFuncSetAttribute(attn_kernel,
                         cudaFuncAttributeMaxDynamicSharedMemorySize,
                         ATTN_SMEM_BYTES);

    qkv_kernel<<<dim3(128, 3), 256>>>(idx, Wq, Wk, Wv);
    attn_kernel<<<dim3(TT / AR, BB), 256, ATTN_SMEM_BYTES>>>(out);
}

// round 3
// speedup vs baseline: 2.2271x; 2.2271x over previous
#include <cuda_runtime.h>
#include <math.h>
#include <stdint.h>

#define BB 4
#define TT 4096
#define CC 2048
#define HH 128
#define NROW (BB * TT)          // 16384

// Scratch for Q, K, V projections: [B*T, H] each, fp32.
__device__ float g_q[NROW * HH];
__device__ float g_k[NROW * HH];
__device__ float g_v[NROW * HH];

// ---------------------------------------------------------------------------
// tf32 helpers
// ---------------------------------------------------------------------------
__device__ __forceinline__ float ftf32(float x) {
    uint32_t u;
    asm("cvt.rna.tf32.f32 %0, %1;" : "=r"(u) : "f"(x));
    return __uint_as_float(u);
}

__device__ __forceinline__ void mma_tf32(float* d, const float* a, const float* b) {
    asm volatile(
        "mma.sync.aligned.m16n8k8.row.col.f32.tf32.tf32.f32 "
        "{%0,%1,%2,%3}, {%4,%5,%6,%7}, {%8,%9}, {%0,%1,%2,%3};"
        : "+f"(d[0]), "+f"(d[1]), "+f"(d[2]), "+f"(d[3])
        : "r"(__float_as_uint(a[0])), "r"(__float_as_uint(a[1])),
          "r"(__float_as_uint(a[2])), "r"(__float_as_uint(a[3])),
          "r"(__float_as_uint(b[0])), "r"(__float_as_uint(b[1])));
}

// ---------------------------------------------------------------------------
// Kernel 1: fused QKV projection.  Out[row, h] = sum_k idx[row,k] * W[h,k]
// BM=128 rows, BN=128 (all H), BK=32.  256 threads = 8 warps (4x2 warp grid:
// each warp 32 rows x 64 cols of output via m16n8k8 tf32 mma).
// grid = (128 row tiles, 3 weights)
// ---------------------------------------------------------------------------
#define QBK 32
#define QKS 36      // smem k-stride (floats): (36*m + k) % 32 == 4*grp+lq -> conflict free

__global__ __launch_bounds__(256, 2)
void qkv_kernel(const float* __restrict__ idx,
                const float* __restrict__ Wq,
                const float* __restrict__ Wk,
                const float* __restrict__ Wv)
{
    __shared__ float As[128][QKS];   // A tile, row-major [m][k]
    __shared__ float Bs[128][QKS];   // W tile, row-major [n][k]

    const int w = blockIdx.y;
    const float* __restrict__ Wp = (w == 0) ? Wq : (w == 1) ? Wk : Wv;
    float* __restrict__ Out = (w == 0) ? g_q : (w == 1) ? g_k : g_v;

    const int row0 = blockIdx.x * 128;
    const int tid  = threadIdx.x;
    const int warp = tid >> 5, lane = tid & 31;
    const int grp  = lane >> 2, lq = lane & 3;
    const int wm   = warp >> 1;          // 0..3 -> m base wm*32 (2 m16 tiles)
    const int wn   = warp & 1;           // 0..1 -> n base wn*64 (8 n8 tiles)

    float acc[2][8][4];
#pragma unroll
    for (int mt = 0; mt < 2; mt++)
#pragma unroll
        for (int nt = 0; nt < 8; nt++)
#pragma unroll
            for (int r = 0; r < 4; r++) acc[mt][nt][r] = 0.f;

    for (int k0 = 0; k0 < CC; k0 += QBK) {
        // Load A (128x32) and B (128x32), tf32-rounded, row-major smem.
#pragma unroll
        for (int i = 0; i < 4; i++) {
            int fi = tid + 256 * i;          // float4 index 0..1023
            int m  = fi >> 3;                // 0..127
            int kq = (fi & 7) * 4;           // 0..28
            float4 va = *(const float4*)(idx + (size_t)(row0 + m) * CC + k0 + kq);
            float4 ta = make_float4(ftf32(va.x), ftf32(va.y), ftf32(va.z), ftf32(va.w));
            *(float4*)&As[m][kq] = ta;
            float4 vb = *(const float4*)(Wp + (size_t)m * CC + k0 + kq);
            float4 tb = make_float4(ftf32(vb.x), ftf32(vb.y), ftf32(vb.z), ftf32(vb.w));
            *(float4*)&Bs[m][kq] = tb;
        }
        __syncthreads();

#pragma unroll
        for (int kk = 0; kk < 4; kk++) {
            const int kb = kk * 8;
            float a[2][4], b[8][2];
#pragma unroll
            for (int mt = 0; mt < 2; mt++) {
                int m = wm * 32 + mt * 16 + grp;
                a[mt][0] = As[m][kb + lq];
                a[mt][1] = As[m + 8][kb + lq];
                a[mt][2] = As[m][kb + lq + 4];
                a[mt][3] = As[m + 8][kb + lq + 4];
            }
#pragma unroll
            for (int nt = 0; nt < 8; nt++) {
                int n = wn * 64 + nt * 8 + grp;
                b[nt][0] = Bs[n][kb + lq];
                b[nt][1] = Bs[n][kb + lq + 4];
            }
#pragma unroll
            for (int mt = 0; mt < 2; mt++)
#pragma unroll
                for (int nt = 0; nt < 8; nt++)
                    mma_tf32(acc[mt][nt], a[mt], b[nt]);
        }
        __syncthreads();
    }

#pragma unroll
    for (int mt = 0; mt < 2; mt++)
#pragma unroll
        for (int nt = 0; nt < 8; nt++) {
            int r = row0 + wm * 32 + mt * 16 + grp;
            int c = wn * 64 + nt * 8 + 2 * lq;
            *(float2*)&Out[(size_t)r * HH + c] =
                make_float2(acc[mt][nt][0], acc[mt][nt][1]);
            *(float2*)&Out[(size_t)(r + 8) * HH + c] =
                make_float2(acc[mt][nt][2], acc[mt][nt][3]);
        }
}

// ---------------------------------------------------------------------------
// Kernel 2: causal attention, flash style, tf32 mma.
// S[i,j] = scale * <k_i, q_j>, softmax over j<=i, O[i,:] = sum_j P[i,j] v_j.
// CTA: 64 i-rows resident (K tile), loops 64-wide j-tiles of Q/V.
// Persistent pairing: each CTA handles i-blocks (p, 63-p) -> 65 j-iters each.
// 256 threads = 8 warps; warp grid 4x2.
// S phase: warp tile m16 x n32.  PV phase: warp tile m16 x n64 (h).
// ---------------------------------------------------------------------------
#define AM 64
#define AN 64
#define KQS 132     // K/Q smem h-stride
#define VST 68      // Vt / Ss smem stride

#define ATTN_SMEM_FLOATS (2 * AM * KQS + HH * VST + AM * VST + 3 * AM)
#define ATTN_SMEM_BYTES  (ATTN_SMEM_FLOATS * 4)

__global__ __launch_bounds__(256, 1)
void attn_kernel(float* __restrict__ out)
{
    extern __shared__ float sm[];
    float* Ks  = sm;                       // [64][132]  K rows (tf32)
    float* Qs  = Ks + AM * KQS;            // [64][132]  Q rows (tf32)
    float* Vt  = Qs + AM * KQS;            // [128][68]  V transposed [h][j] (tf32)
    float* Ss  = Vt + HH * VST;            // [64][68]   scores / probs
    float* m_s = Ss + AM * VST;            // [64]
    float* l_s = m_s + AM;                 // [64]
    float* a_s = l_s + AM;                 // [64]

    const int b    = blockIdx.y;
    const int pair = blockIdx.x;           // 0..31
    const int tid  = threadIdx.x;
    const int warp = tid >> 5, lane = tid & 31;
    const int grp  = lane >> 2, lq = lane & 3;
    const int wm   = warp >> 1;            // m16 tile: rows wm*16
    const int wn   = warp & 1;

    const float scale = rsqrtf((float)CC);

    for (int phase = 0; phase < 2; phase++) {
        const int ib = (phase == 0) ? pair : 63 - pair;
        const int i0 = ib * AM;

        // Load resident K tile (tf32-rounded)
        const float* kbase = g_k + ((size_t)b * TT + i0) * HH;
#pragma unroll
        for (int i = 0; i < 8; i++) {
            int fi = tid + 256 * i;          // 2048 float4
            int r  = fi >> 5;                // 0..63
            int c  = (fi & 31) * 4;          // 0..124
            float4 v = *(const float4*)(kbase + r * HH + c);
            *(float4*)&Ks[r * KQS + c] =
                make_float4(ftf32(v.x), ftf32(v.y), ftf32(v.z), ftf32(v.w));
        }
        if (tid < AM) { m_s[tid] = -INFINITY; l_s[tid] = 0.f; }

        float o[8][4];                       // m16 x n64 (8 n8 tiles)
#pragma unroll
        for (int nt = 0; nt < 8; nt++)
#pragma unroll
            for (int r = 0; r < 4; r++) o[nt][r] = 0.f;
        __syncthreads();

        for (int jb = 0; jb <= ib; jb++) {
            const int j0 = jb * AN;
            const float* qb = g_q + ((size_t)b * TT + j0) * HH;
            const float* vb = g_v + ((size_t)b * TT + j0) * HH;
#pragma unroll
            for (int i = 0; i < 8; i++) {
                int fi = tid + 256 * i;
                int r  = fi >> 5;
                int c  = (fi & 31) * 4;
                float4 vq = *(const float4*)(qb + r * HH + c);
                *(float4*)&Qs[r * KQS + c] =
                    make_float4(ftf32(vq.x), ftf32(vq.y), ftf32(vq.z), ftf32(vq.w));
                float4 vv = *(const float4*)(vb + r * HH + c);
                Vt[(c + 0) * VST + r] = ftf32(vv.x);
                Vt[(c + 1) * VST + r] = ftf32(vv.y);
                Vt[(c + 2) * VST + r] = ftf32(vv.z);
                Vt[(c + 3) * VST + r] = ftf32(vv.w);
            }
            __syncthreads();

            // ---- S = Ks . Qs^T : warp tile m16 (rows wm*16) x n32 (cols wn*32)
            float sfr[4][4];
#pragma unroll
            for (int nt = 0; nt < 4; nt++)
#pragma unroll
                for (int r = 0; r < 4; r++) sfr[nt][r] = 0.f;

            const int mrow = wm * 16 + grp;
#pragma unroll
            for (int kk = 0; kk < 16; kk++) {
                const int kb = kk * 8;
                float a[4], bq[4][2];
                a[0] = Ks[mrow * KQS + kb + lq];
                a[1] = Ks[(mrow + 8) * KQS + kb + lq];
                a[2] = Ks[mrow * KQS + kb + lq + 4];
                a[3] = Ks[(mrow + 8) * KQS + kb + lq + 4];
#pragma unroll
                for (int nt = 0; nt < 4; nt++) {
                    int n = wn * 32 + nt * 8 + grp;
                    bq[nt][0] = Qs[n * KQS + kb + lq];
                    bq[nt][1] = Qs[n * KQS + kb + lq + 4];
                }
#pragma unroll
                for (int nt = 0; nt < 4; nt++) mma_tf32(sfr[nt], a, bq[nt]);
            }

            // scale + causal mask + store to Ss
#pragma unroll
            for (int nt = 0; nt < 4; nt++) {
                int c = wn * 32 + nt * 8 + 2 * lq;
                int r = wm * 16 + grp;
                float v0 = sfr[nt][0] * scale, v1 = sfr[nt][1] * scale;
                float v2 = sfr[nt][2] * scale, v3 = sfr[nt][3] * scale;
                if (jb == ib) {              // diagonal tile: mask j > i
                    if (c > r)         v0 = -INFINITY;
                    if (c + 1 > r)     v1 = -INFINITY;
                    if (c > r + 8)     v2 = -INFINITY;
                    if (c + 1 > r + 8) v3 = -INFINITY;
                }
                *(float2*)&Ss[r * VST + c]       = make_float2(v0, v1);
                *(float2*)&Ss[(r + 8) * VST + c] = make_float2(v2, v3);
            }
            __syncthreads();

            // ---- online softmax: 4 threads per row, 16 cols each
            {
                const int row = tid >> 2;
                const int q4  = tid & 3;
                float* srow = Ss + row * VST + q4 * 16;
                float mx = -INFINITY;
#pragma unroll
                for (int c = 0; c < 16; c++) mx = fmaxf(mx, srow[c]);
                mx = fmaxf(mx, __shfl_xor_sync(0xffffffffu, mx, 1));
                mx = fmaxf(mx, __shfl_xor_sync(0xffffffffu, mx, 2));
                const float m_old = m_s[row];
                const float m_new = fmaxf(m_old, mx);
                float ps = 0.f;
#pragma unroll
                for (int c = 0; c < 16; c++) {
                    float p = __expf(srow[c] - m_new);
                    ps += p;
                    srow[c] = ftf32(p);      // P consumed by tf32 mma
                }
                ps += __shfl_xor_sync(0xffffffffu, ps, 1);
                ps += __shfl_xor_sync(0xffffffffu, ps, 2);
                if (q4 == 0) {
                    const float al = __expf(m_old - m_new);
                    a_s[row] = al;
                    l_s[row] = l_s[row] * al + ps;
                    m_s[row] = m_new;
                }
            }
            __syncthreads();

            // ---- O = O*alpha + P @ V : warp tile m16 x n64 (cols wn*64)
            {
                const float al0 = a_s[mrow];
                const float al1 = a_s[mrow + 8];
#pragma unroll
                for (int nt = 0; nt < 8; nt++) {
                    o[nt][0] *= al0; o[nt][1] *= al0;
                    o[nt][2] *= al1; o[nt][3] *= al1;
                }
#pragma unroll
                for (int kk = 0; kk < 8; kk++) {
                    const int kb = kk * 8;
                    float a[4], bv[8][2];
                    a[0] = Ss[mrow * VST + kb + lq];
                    a[1] = Ss[(mrow + 8) * VST + kb + lq];
                    a[2] = Ss[mrow * VST + kb + lq + 4];
                    a[3] = Ss[(mrow + 8) * VST + kb + lq + 4];
#pragma unroll
                    for (int nt = 0; nt < 8; nt++) {
                        int n = wn * 64 + nt * 8 + grp;   // h index
                        bv[nt][0] = Vt[n * VST + kb + lq];
                        bv[nt][1] = Vt[n * VST + kb + lq + 4];
                    }
#pragma unroll
                    for (int nt = 0; nt < 8; nt++) mma_tf32(o[nt], a, bv[nt]);
                }
            }
            __syncthreads();   // protect Qs/Vt/Ss before next tile load
        }

        // ---- epilogue: divide by l, write out
        const int mrow = wm * 16 + grp;
        const float inv0 = 1.f / l_s[mrow];
        const float inv1 = 1.f / l_s[mrow + 8];
        float* obase = out + ((size_t)b * TT + i0) * HH;
#pragma unroll
        for (int nt = 0; nt < 8; nt++) {
            int c = wn * 64 + nt * 8 + 2 * lq;
            *(float2*)&obase[(size_t)mrow * HH + c] =
                make_float2(o[nt][0] * inv0, o[nt][1] * inv0);
            *(float2*)&obase[(size_t)(mrow + 8) * HH + c] =
                make_float2(o[nt][2] * inv1, o[nt][3] * inv1);
        }
        __syncthreads();   // all done with smem before next phase reloads
    }
}

// ---------------------------------------------------------------------------
extern "C" void kernel_launch(void* const* d_in, const int* in_sizes, int n_in,
                              void* d_out, int out_size)
{
    const float* idx = (const float*)d_in[0];
    const float* Wq  = (const float*)d_in[1];
    const float* Wk  = (const float*)d_in[2];
    const float* Wv  = (const float*)d_in[3];
    float* out = (float*)d_out;

    cudaFuncSetAttribute(attn_kernel,
                         cudaFuncAttributeMaxDynamicSharedMemorySize,
                         ATTN_SMEM_BYTES);

    qkv_kernel<<<dim3(NROW / 128, 3), 256>>>(idx, Wq, Wk, Wv);
    attn_kernel<<<dim3(32, BB), 256, ATTN_SMEM_BYTES>>>(out);
}